// round 1
// baseline (speedup 1.0000x reference)
#include <cuda_runtime.h>

#define HH 256
#define WW 256
#define NI 16
#define CC 3
#define HW (HH * WW)

__global__ __launch_bounds__(256)
void warp_renderer_kernel(
    const float* __restrict__ g0,           // [B,NI,C,H,W]
    const float* __restrict__ m0,           // [B,NI,1,H,W]
    const float* __restrict__ mode_logits,  // [B,NI,5]
    const float* __restrict__ tp,           // [B,NI,6]
    const float* __restrict__ alpha,        // [B,NI,1]
    const float* __restrict__ inst_valid,   // [B,NI]
    const float* __restrict__ i_bg,         // [B,C,H,W]
    float* __restrict__ out,
    int B)
{
    __shared__ float s_t[NI][6];
    __shared__ float s_coef[NI];

    const int b = blockIdx.x >> 8;        // blockIdx.x = b*H + y
    const int y = blockIdx.x & 255;
    const int x = threadIdx.x;

    // --- per-instance precompute (threads 0..15) ---
    if (threadIdx.x < NI) {
        const int inst = b * NI + threadIdx.x;
        const float* L = mode_logits + (size_t)inst * 5;
        int mode = 0;
        float best = L[0];
        #pragma unroll
        for (int k = 1; k < 5; ++k) {
            float v = L[k];
            if (v > best) { best = v; mode = k; }  // first-max argmax
        }
        float coef;
        if (mode == 0 || mode == 2 || mode == 4) coef = 1.0f;       // static-like
        else if (mode == 3)                      coef = alpha[inst]; // blink
        else                                     coef = 0.0f;        // mode 1
        coef *= inst_valid[inst];
        s_coef[threadIdx.x] = coef;
        #pragma unroll
        for (int k = 0; k < 6; ++k) s_t[threadIdx.x][k] = tp[(size_t)inst * 6 + k];
    }
    __syncthreads();

    const float xs = (2.0f * (float)x + 1.0f) / (float)WW - 1.0f;
    const float ys = (2.0f * (float)y + 1.0f) / (float)HH - 1.0f;
    const int pix = y * WW + x;

    // output section pointers
    const size_t n_gpi = (size_t)B * NI * CC * HW;
    const size_t n_mpi = (size_t)B * NI * HW;
    float* __restrict__ out_gpi  = out;
    float* __restrict__ out_mpi  = out + n_gpi;
    float* __restrict__ out_gmid = out + n_gpi + n_mpi;
    float* __restrict__ out_mmid = out_gmid + (size_t)B * CC * HW;
    float* __restrict__ out_ibas = out_mmid + (size_t)B * HW;

    float gacc0 = 0.0f, gacc1 = 0.0f, gacc2 = 0.0f, macc = 0.0f;

    #pragma unroll 1
    for (int ni = 0; ni < NI; ++ni) {
        const size_t base_g = (((size_t)b * NI + ni) * CC) * HW;
        const size_t base_m = ((size_t)b * NI + ni) * HW;
        const float coef = s_coef[ni];

        if (coef == 0.0f) {
            out_gpi[base_g + pix]            = 0.0f;
            out_gpi[base_g + HW + pix]       = 0.0f;
            out_gpi[base_g + 2 * HW + pix]   = 0.0f;
            out_mpi[base_m + pix]            = 0.0f;
            continue;
        }

        const float t0 = s_t[ni][0], t1 = s_t[ni][1], t2 = s_t[ni][2];
        const float t3 = s_t[ni][3], t4 = s_t[ni][4], t5 = s_t[ni][5];

        const float gx = t0 * xs + t1 * ys + t2;
        const float gy = t3 * xs + t4 * ys + t5;
        const float ix = ((gx + 1.0f) * (float)WW - 1.0f) * 0.5f;
        const float iy = ((gy + 1.0f) * (float)HH - 1.0f) * 0.5f;

        const float x0f = floorf(ix), y0f = floorf(iy);
        const float wx1 = ix - x0f, wy1 = iy - y0f;
        const float wx0 = 1.0f - wx1, wy0 = 1.0f - wy1;

        const int x0 = (int)x0f, y0 = (int)y0f;
        const int x1 = x0 + 1,   y1 = y0 + 1;

        const bool vx0 = (x0 >= 0) & (x0 < WW);
        const bool vx1 = (x1 >= 0) & (x1 < WW);
        const bool vy0 = (y0 >= 0) & (y0 < HH);
        const bool vy1 = (y1 >= 0) & (y1 < HH);

        const int x0c = min(max(x0, 0), WW - 1);
        const int x1c = min(max(x1, 0), WW - 1);
        const int y0c = min(max(y0, 0), HH - 1);
        const int y1c = min(max(y1, 0), HH - 1);

        const float w00 = wx0 * wy0 * ((vx0 & vy0) ? 1.0f : 0.0f);
        const float w10 = wx1 * wy0 * ((vx1 & vy0) ? 1.0f : 0.0f);
        const float w01 = wx0 * wy1 * ((vx0 & vy1) ? 1.0f : 0.0f);
        const float w11 = wx1 * wy1 * ((vx1 & vy1) ? 1.0f : 0.0f);

        const int i00 = y0c * WW + x0c;
        const int i10 = y0c * WW + x1c;
        const int i01 = y1c * WW + x0c;
        const int i11 = y1c * WW + x1c;

        // overlay channels
        float gr[CC];
        #pragma unroll
        for (int c = 0; c < CC; ++c) {
            const float* __restrict__ src = g0 + base_g + (size_t)c * HW;
            float v = w00 * __ldg(src + i00) + w10 * __ldg(src + i10)
                    + w01 * __ldg(src + i01) + w11 * __ldg(src + i11);
            gr[c] = coef * v;
            out_gpi[base_g + (size_t)c * HW + pix] = gr[c];
        }
        gacc0 += gr[0]; gacc1 += gr[1]; gacc2 += gr[2];

        // mask channel
        {
            const float* __restrict__ src = m0 + base_m;
            float v = w00 * __ldg(src + i00) + w10 * __ldg(src + i10)
                    + w01 * __ldg(src + i01) + w11 * __ldg(src + i11);
            float rm = coef * v;
            out_mpi[base_m + pix] = rm;
            macc += rm;
        }
    }

    // reductions + composite
    const size_t bg = (size_t)b * CC * HW;
    out_gmid[bg + pix]          = gacc0;
    out_gmid[bg + HW + pix]     = gacc1;
    out_gmid[bg + 2 * HW + pix] = gacc2;
    out_mmid[(size_t)b * HW + pix] = fminf(fmaxf(macc, 0.0f), 1.0f);
    out_ibas[bg + pix]          = i_bg[bg + pix]          + gacc0;
    out_ibas[bg + HW + pix]     = i_bg[bg + HW + pix]     + gacc1;
    out_ibas[bg + 2 * HW + pix] = i_bg[bg + 2 * HW + pix] + gacc2;
}

extern "C" void kernel_launch(void* const* d_in, const int* in_sizes, int n_in,
                              void* d_out, int out_size) {
    const float* g0          = (const float*)d_in[0];
    const float* m0          = (const float*)d_in[1];
    const float* mode_logits = (const float*)d_in[2];
    const float* tp          = (const float*)d_in[3];
    const float* alpha       = (const float*)d_in[4];
    const float* inst_valid  = (const float*)d_in[5];
    const float* i_bg        = (const float*)d_in[6];
    float* out = (float*)d_out;

    const int B = in_sizes[0] / (NI * CC * HW);

    dim3 grid(B * HH);
    dim3 block(WW);
    warp_renderer_kernel<<<grid, block>>>(g0, m0, mode_logits, tp, alpha,
                                          inst_valid, i_bg, out, B);
}

// round 2
// speedup vs baseline: 1.1242x; 1.1242x over previous
#include <cuda_runtime.h>

#define HH 256
#define WW 256
#define NI 16
#define CC 3
#define HW (HH * WW)

__global__ __launch_bounds__(256, 7)
void warp_renderer_kernel(
    const float* __restrict__ g0,           // [B,NI,C,H,W]
    const float* __restrict__ m0,           // [B,NI,1,H,W]
    const float* __restrict__ mode_logits,  // [B,NI,5]
    const float* __restrict__ tp,           // [B,NI,6]
    const float* __restrict__ alpha,        // [B,NI,1]
    const float* __restrict__ inst_valid,   // [B,NI]
    const float* __restrict__ i_bg,         // [B,C,H,W]
    float* __restrict__ out,
    int B)
{
    __shared__ int   s_nact, s_ninact;
    __shared__ int   s_act_ni[NI];
    __shared__ float s_act_coef[NI];
    __shared__ float s_act_t0[NI], s_act_t3[NI];
    __shared__ float s_act_bx[NI], s_act_by[NI];
    __shared__ int   s_inact_ni[NI];

    const int b = blockIdx.x >> 8;        // blockIdx.x = b*H + y
    const int y = blockIdx.x & 255;
    const int x = threadIdx.x;

    // --- per-instance precompute + active compaction (lanes 0..15 of warp 0) ---
    if (threadIdx.x < NI) {
        const int lane = threadIdx.x;
        const int inst = b * NI + lane;
        const float* L = mode_logits + inst * 5;
        int mode = 0;
        float best = L[0];
        #pragma unroll
        for (int k = 1; k < 5; ++k) {
            float v = L[k];
            if (v > best) { best = v; mode = k; }  // first-max argmax
        }
        float coef;
        if (mode == 0 || mode == 2 || mode == 4) coef = 1.0f;       // static-like
        else if (mode == 3)                      coef = alpha[inst]; // blink
        else                                     coef = 0.0f;        // mode 1
        coef *= inst_valid[inst];

        const bool active = (coef != 0.0f);
        const unsigned mask = __ballot_sync(0x0000FFFFu, active);
        const unsigned lower = (1u << lane) - 1u;

        if (active) {
            const int pos = __popc(mask & lower);
            const float t0 = tp[inst * 6 + 0];
            const float t1 = tp[inst * 6 + 1];
            const float t2 = tp[inst * 6 + 2];
            const float t3 = tp[inst * 6 + 3];
            const float t4 = tp[inst * 6 + 4];
            const float t5 = tp[inst * 6 + 5];
            const float ys = (2.0f * (float)y + 1.0f) * (1.0f / (float)HH) - 1.0f;
            // ix = t0*x + bx ; iy = t3*x + by   (full chain folded)
            const float bx = 128.0f * (t1 * ys + t2) + 127.5f + 0.5f * t0 - 128.0f * t0;
            const float by = 128.0f * (t4 * ys + t5) + 127.5f + 0.5f * t3 - 128.0f * t3;
            s_act_ni[pos]   = lane;
            s_act_coef[pos] = coef;
            s_act_t0[pos]   = t0;
            s_act_t3[pos]   = t3;
            s_act_bx[pos]   = bx;
            s_act_by[pos]   = by;
        } else {
            const int pos = __popc((~mask) & 0xFFFFu & lower);
            s_inact_ni[pos] = lane;
        }
        if (lane == 0) {
            s_nact   = __popc(mask);
            s_ninact = NI - __popc(mask);
        }
    }
    __syncthreads();

    const int pix = y * WW + x;
    const float xf = (float)x;

    // output section offsets (all < 2^31 elements)
    const int n_gpi = B * NI * CC * HW;
    const int n_mpi = B * NI * HW;
    float* __restrict__ out_gpi  = out;
    float* __restrict__ out_mpi  = out + n_gpi;
    float* __restrict__ out_gmid = out + n_gpi + n_mpi;
    float* __restrict__ out_mmid = out_gmid + B * CC * HW;
    float* __restrict__ out_ibas = out_mmid + B * HW;

    // --- zero stores for inactive instances ---
    const int ninact = s_ninact;
    for (int k = 0; k < ninact; ++k) {
        const int ni = s_inact_ni[k];
        const int bgi = (b * NI + ni) * CC * HW + pix;
        const int bmi = (b * NI + ni) * HW + pix;
        out_gpi[bgi]          = 0.0f;
        out_gpi[bgi + HW]     = 0.0f;
        out_gpi[bgi + 2 * HW] = 0.0f;
        out_mpi[bmi]          = 0.0f;
    }

    float gacc0 = 0.0f, gacc1 = 0.0f, gacc2 = 0.0f, macc = 0.0f;

    // --- hot loop: active instances only, no branches ---
    const int nact = s_nact;
    for (int j = 0; j < nact; ++j) {
        const int   ni   = s_act_ni[j];
        const float coef = s_act_coef[j];
        const int base_g = (b * NI + ni) * CC * HW;
        const int base_m = (b * NI + ni) * HW;

        const float ix = fmaf(s_act_t0[j], xf, s_act_bx[j]);
        const float iy = fmaf(s_act_t3[j], xf, s_act_by[j]);

        const float x0f = floorf(ix), y0f = floorf(iy);
        const float wx1 = ix - x0f, wy1 = iy - y0f;
        const float wx0 = 1.0f - wx1, wy0 = 1.0f - wy1;

        const int x0 = (int)x0f, y0 = (int)y0f;
        const int x1 = x0 + 1,   y1 = y0 + 1;

        const bool vx0 = (x0 >= 0) & (x0 < WW);
        const bool vx1 = (x1 >= 0) & (x1 < WW);
        const bool vy0 = (y0 >= 0) & (y0 < HH);
        const bool vy1 = (y1 >= 0) & (y1 < HH);

        const int x0c = min(max(x0, 0), WW - 1);
        const int x1c = min(max(x1, 0), WW - 1);
        const int y0c = min(max(y0, 0), HH - 1);
        const int y1c = min(max(y1, 0), HH - 1);

        const float w00 = wx0 * wy0 * ((vx0 & vy0) ? 1.0f : 0.0f);
        const float w10 = wx1 * wy0 * ((vx1 & vy0) ? 1.0f : 0.0f);
        const float w01 = wx0 * wy1 * ((vx0 & vy1) ? 1.0f : 0.0f);
        const float w11 = wx1 * wy1 * ((vx1 & vy1) ? 1.0f : 0.0f);

        const int i00 = y0c * WW + x0c;
        const int i10 = y0c * WW + x1c;
        const int i01 = y1c * WW + x0c;
        const int i11 = y1c * WW + x1c;

        // overlay channels (12 independent loads)
        const float* __restrict__ s0 = g0 + base_g;
        const float* __restrict__ s1 = s0 + HW;
        const float* __restrict__ s2 = s1 + HW;
        const float a00 = __ldg(s0 + i00), a10 = __ldg(s0 + i10),
                    a01 = __ldg(s0 + i01), a11 = __ldg(s0 + i11);
        const float b00 = __ldg(s1 + i00), b10 = __ldg(s1 + i10),
                    b01 = __ldg(s1 + i01), b11 = __ldg(s1 + i11);
        const float c00 = __ldg(s2 + i00), c10 = __ldg(s2 + i10),
                    c01 = __ldg(s2 + i01), c11 = __ldg(s2 + i11);
        // mask (4 loads)
        const float* __restrict__ sm = m0 + base_m;
        const float d00 = __ldg(sm + i00), d10 = __ldg(sm + i10),
                    d01 = __ldg(sm + i01), d11 = __ldg(sm + i11);

        const float g0v = coef * (w00 * a00 + w10 * a10 + w01 * a01 + w11 * a11);
        const float g1v = coef * (w00 * b00 + w10 * b10 + w01 * b01 + w11 * b11);
        const float g2v = coef * (w00 * c00 + w10 * c10 + w01 * c01 + w11 * c11);
        const float mv  = coef * (w00 * d00 + w10 * d10 + w01 * d01 + w11 * d11);

        out_gpi[base_g + pix]          = g0v;
        out_gpi[base_g + HW + pix]     = g1v;
        out_gpi[base_g + 2 * HW + pix] = g2v;
        out_mpi[base_m + pix]          = mv;

        gacc0 += g0v; gacc1 += g1v; gacc2 += g2v; macc += mv;
    }

    // --- reductions + composite ---
    const int bg = b * CC * HW + pix;
    out_gmid[bg]          = gacc0;
    out_gmid[bg + HW]     = gacc1;
    out_gmid[bg + 2 * HW] = gacc2;
    out_mmid[b * HW + pix] = fminf(fmaxf(macc, 0.0f), 1.0f);
    out_ibas[bg]          = i_bg[bg]          + gacc0;
    out_ibas[bg + HW]     = i_bg[bg + HW]     + gacc1;
    out_ibas[bg + 2 * HW] = i_bg[bg + 2 * HW] + gacc2;
}

extern "C" void kernel_launch(void* const* d_in, const int* in_sizes, int n_in,
                              void* d_out, int out_size) {
    const float* g0          = (const float*)d_in[0];
    const float* m0          = (const float*)d_in[1];
    const float* mode_logits = (const float*)d_in[2];
    const float* tp          = (const float*)d_in[3];
    const float* alpha       = (const float*)d_in[4];
    const float* inst_valid  = (const float*)d_in[5];
    const float* i_bg        = (const float*)d_in[6];
    float* out = (float*)d_out;

    const int B = in_sizes[0] / (NI * CC * HW);

    dim3 grid(B * HH);
    dim3 block(WW);
    warp_renderer_kernel<<<grid, block>>>(g0, m0, mode_logits, tp, alpha,
                                          inst_valid, i_bg, out, B);
}

// round 3
// speedup vs baseline: 1.1906x; 1.0591x over previous
#include <cuda_runtime.h>

#define HH 256
#define WW 256
#define NI 16
#define CC 3
#define HW (HH * WW)

struct Tap { int i00, i10, i01, i11; float w00, w10, w01, w11; };

__device__ __forceinline__ Tap make_tap(float ix, float iy) {
    Tap t;
    const float x0f = floorf(ix), y0f = floorf(iy);
    const float wx1 = ix - x0f, wy1 = iy - y0f;
    const float wx0 = 1.0f - wx1, wy0 = 1.0f - wy1;
    const int x0 = (int)x0f, y0 = (int)y0f;
    const int x1 = x0 + 1,   y1 = y0 + 1;
    const bool vx0 = (x0 >= 0) & (x0 < WW);
    const bool vx1 = (x1 >= 0) & (x1 < WW);
    const bool vy0 = (y0 >= 0) & (y0 < HH);
    const bool vy1 = (y1 >= 0) & (y1 < HH);
    const int x0c = min(max(x0, 0), WW - 1);
    const int x1c = min(max(x1, 0), WW - 1);
    const int y0c = min(max(y0, 0), HH - 1);
    const int y1c = min(max(y1, 0), HH - 1);
    t.w00 = wx0 * wy0 * ((vx0 & vy0) ? 1.0f : 0.0f);
    t.w10 = wx1 * wy0 * ((vx1 & vy0) ? 1.0f : 0.0f);
    t.w01 = wx0 * wy1 * ((vx0 & vy1) ? 1.0f : 0.0f);
    t.w11 = wx1 * wy1 * ((vx1 & vy1) ? 1.0f : 0.0f);
    t.i00 = y0c * WW + x0c;
    t.i10 = y0c * WW + x1c;
    t.i01 = y1c * WW + x0c;
    t.i11 = y1c * WW + x1c;
    return t;
}

__device__ __forceinline__ float gather(const float* __restrict__ p, const Tap& t) {
    return t.w00 * __ldg(p + t.i00) + t.w10 * __ldg(p + t.i10)
         + t.w01 * __ldg(p + t.i01) + t.w11 * __ldg(p + t.i11);
}

__global__ __launch_bounds__(128, 8)
void warp_renderer_kernel(
    const float* __restrict__ g0,           // [B,NI,C,H,W]
    const float* __restrict__ m0,           // [B,NI,1,H,W]
    const float* __restrict__ mode_logits,  // [B,NI,5]
    const float* __restrict__ tp,           // [B,NI,6]
    const float* __restrict__ alpha,        // [B,NI,1]
    const float* __restrict__ inst_valid,   // [B,NI]
    const float* __restrict__ i_bg,         // [B,C,H,W]
    float* __restrict__ out,
    int B)
{
    __shared__ int   s_nact, s_ninact;
    __shared__ int   s_act_ni[NI];
    __shared__ float s_act_coef[NI];
    __shared__ float s_act_t0[NI], s_act_t3[NI];
    __shared__ float s_act_bx[NI], s_act_by[NI];
    __shared__ int   s_inact_ni[NI];

    const int b = blockIdx.x >> 8;        // blockIdx.x = b*H + y
    const int y = blockIdx.x & 255;

    // --- per-instance precompute + active compaction (lanes 0..15 of warp 0) ---
    if (threadIdx.x < NI) {
        const int lane = threadIdx.x;
        const int inst = b * NI + lane;
        const float* L = mode_logits + inst * 5;
        int mode = 0;
        float best = L[0];
        #pragma unroll
        for (int k = 1; k < 5; ++k) {
            float v = L[k];
            if (v > best) { best = v; mode = k; }  // first-max argmax
        }
        float coef;
        if (mode == 0 || mode == 2 || mode == 4) coef = 1.0f;       // static-like
        else if (mode == 3)                      coef = alpha[inst]; // blink
        else                                     coef = 0.0f;        // mode 1
        coef *= inst_valid[inst];

        const bool active = (coef != 0.0f);
        const unsigned mask = __ballot_sync(0x0000FFFFu, active);
        const unsigned lower = (1u << lane) - 1u;

        if (active) {
            const int pos = __popc(mask & lower);
            const float t0 = tp[inst * 6 + 0];
            const float t1 = tp[inst * 6 + 1];
            const float t2 = tp[inst * 6 + 2];
            const float t3 = tp[inst * 6 + 3];
            const float t4 = tp[inst * 6 + 4];
            const float t5 = tp[inst * 6 + 5];
            const float ys = (2.0f * (float)y + 1.0f) * (1.0f / (float)HH) - 1.0f;
            // ix = t0*x + bx ; iy = t3*x + by   (full chain folded)
            const float bx = 128.0f * (t1 * ys + t2) + 127.5f + 0.5f * t0 - 128.0f * t0;
            const float by = 128.0f * (t4 * ys + t5) + 127.5f + 0.5f * t3 - 128.0f * t3;
            s_act_ni[pos]   = lane;
            s_act_coef[pos] = coef;
            s_act_t0[pos]   = t0;
            s_act_t3[pos]   = t3;
            s_act_bx[pos]   = bx;
            s_act_by[pos]   = by;
        } else {
            const int pos = __popc((~mask) & 0xFFFFu & lower);
            s_inact_ni[pos] = lane;
        }
        if (lane == 0) {
            s_nact   = __popc(mask);
            s_ninact = NI - __popc(mask);
        }
    }
    __syncthreads();

    const int x0px = threadIdx.x * 2;           // first of the two pixels
    const int pix = y * WW + x0px;              // float2-aligned
    const float xf0 = (float)x0px;

    // output section offsets (all < 2^31 elements)
    const int n_gpi = B * NI * CC * HW;
    const int n_mpi = B * NI * HW;
    float* __restrict__ out_gpi  = out;
    float* __restrict__ out_mpi  = out + n_gpi;
    float* __restrict__ out_gmid = out + n_gpi + n_mpi;
    float* __restrict__ out_mmid = out_gmid + B * CC * HW;
    float* __restrict__ out_ibas = out_mmid + B * HW;

    // --- zero stores for inactive instances (float2) ---
    const float2 z2 = make_float2(0.0f, 0.0f);
    const int ninact = s_ninact;
    for (int k = 0; k < ninact; ++k) {
        const int ni = s_inact_ni[k];
        const int bgi = (b * NI + ni) * CC * HW + pix;
        const int bmi = (b * NI + ni) * HW + pix;
        *(float2*)(out_gpi + bgi)          = z2;
        *(float2*)(out_gpi + bgi + HW)     = z2;
        *(float2*)(out_gpi + bgi + 2 * HW) = z2;
        *(float2*)(out_mpi + bmi)          = z2;
    }

    float ga0 = 0.0f, ga1 = 0.0f;   // channel 0, px0/px1
    float gb0 = 0.0f, gb1 = 0.0f;   // channel 1
    float gc0 = 0.0f, gc1 = 0.0f;   // channel 2
    float ma0 = 0.0f, ma1 = 0.0f;   // mask

    // --- hot loop: active instances only, no branches ---
    const int nact = s_nact;
    for (int j = 0; j < nact; ++j) {
        const int   ni   = s_act_ni[j];
        const float coef = s_act_coef[j];
        const float t0   = s_act_t0[j];
        const float t3   = s_act_t3[j];
        const int base_g = (b * NI + ni) * CC * HW;
        const int base_m = (b * NI + ni) * HW;

        const float ix0 = fmaf(t0, xf0, s_act_bx[j]);
        const float iy0 = fmaf(t3, xf0, s_act_by[j]);
        const float ix1 = ix0 + t0;
        const float iy1 = iy0 + t3;

        const Tap ta = make_tap(ix0, iy0);
        const Tap tb = make_tap(ix1, iy1);

        const float* __restrict__ s0 = g0 + base_g;
        const float* __restrict__ s1 = s0 + HW;
        const float* __restrict__ s2 = s1 + HW;
        const float* __restrict__ sm = m0 + base_m;

        const float A0 = gather(s0, ta), A1 = gather(s0, tb);
        const float B0 = gather(s1, ta), B1 = gather(s1, tb);
        const float C0 = gather(s2, ta), C1 = gather(s2, tb);
        const float M0 = gather(sm, ta), M1 = gather(sm, tb);

        const float2 gv0 = make_float2(coef * A0, coef * A1);
        const float2 gv1 = make_float2(coef * B0, coef * B1);
        const float2 gv2 = make_float2(coef * C0, coef * C1);
        const float2 mv  = make_float2(coef * M0, coef * M1);

        *(float2*)(out_gpi + base_g + pix)          = gv0;
        *(float2*)(out_gpi + base_g + HW + pix)     = gv1;
        *(float2*)(out_gpi + base_g + 2 * HW + pix) = gv2;
        *(float2*)(out_mpi + base_m + pix)          = mv;

        ga0 += gv0.x; ga1 += gv0.y;
        gb0 += gv1.x; gb1 += gv1.y;
        gc0 += gv2.x; gc1 += gv2.y;
        ma0 += mv.x;  ma1 += mv.y;
    }

    // --- reductions + composite (float2) ---
    const int bg = b * CC * HW + pix;
    *(float2*)(out_gmid + bg)          = make_float2(ga0, ga1);
    *(float2*)(out_gmid + bg + HW)     = make_float2(gb0, gb1);
    *(float2*)(out_gmid + bg + 2 * HW) = make_float2(gc0, gc1);
    *(float2*)(out_mmid + b * HW + pix) =
        make_float2(fminf(fmaxf(ma0, 0.0f), 1.0f), fminf(fmaxf(ma1, 0.0f), 1.0f));

    const float2 bg0 = *(const float2*)(i_bg + bg);
    const float2 bg1 = *(const float2*)(i_bg + bg + HW);
    const float2 bg2 = *(const float2*)(i_bg + bg + 2 * HW);
    *(float2*)(out_ibas + bg)          = make_float2(bg0.x + ga0, bg0.y + ga1);
    *(float2*)(out_ibas + bg + HW)     = make_float2(bg1.x + gb0, bg1.y + gb1);
    *(float2*)(out_ibas + bg + 2 * HW) = make_float2(bg2.x + gc0, bg2.y + gc1);
}

extern "C" void kernel_launch(void* const* d_in, const int* in_sizes, int n_in,
                              void* d_out, int out_size) {
    const float* g0          = (const float*)d_in[0];
    const float* m0          = (const float*)d_in[1];
    const float* mode_logits = (const float*)d_in[2];
    const float* tp          = (const float*)d_in[3];
    const float* alpha       = (const float*)d_in[4];
    const float* inst_valid  = (const float*)d_in[5];
    const float* i_bg        = (const float*)d_in[6];
    float* out = (float*)d_out;

    const int B = in_sizes[0] / (NI * CC * HW);

    dim3 grid(B * HH);
    dim3 block(WW / 2);   // 128 threads, 2 px each
    warp_renderer_kernel<<<grid, block>>>(g0, m0, mode_logits, tp, alpha,
                                          inst_valid, i_bg, out, B);
}